// round 16
// baseline (speedup 1.0000x reference)
#include <cuda_runtime.h>
#include <cuda_fp16.h>
#include <math.h>
#include <stdint.h>

#define E_ 172
#define KP 176            // padded K (11 k16 steps)
#define KSTEPS 11
#define C4 (KP / 4)
#define NSEG 192
#define KNB 20
#define HH 2
#define HD_ 86
#define NNODES 100000
#define BMAX 12000
#define BPAD 12032
#define NPADN 100096
#define NSLOT 240000
#define HTSZ (1 << 19)

// disjoint A-buffer row regions
#define R_EDGE 0
#define R_TIME 240000
#define R_NODE 252032
#define R_Q0   352128
#define R_O    364160
#define AROWS  376192

#define P1_OFF 0      // tqkv weights [q|kE|vE] (+biases)
#define P2_OFF 576    // node kv [kE|vE]
#define P3_OFF 960    // edge kv [kD|vD]
#define P4_OFF 1344   // q proj
#define P5_OFF 1536   // out proj (+out_b)
#define P6_OFF 1728   // composed Wc = Wqkv @ out_w (+ Wqkv@out_b)
#define PTOT 2304

// ---------------- scratch ----------------
__device__ __half g_A[(size_t)AROWS * KP];
__device__ __half g_W[(size_t)PTOT * KP];
__device__ float g_Wb[PTOT];

__device__ __half g_tqkv[BMAX * 576];
__device__ __half g_node_kv[(size_t)NNODES * 384];
__device__ __half g_edge_kv[(size_t)NSLOT * 384];
__device__ __half g_l1out[BMAX * 576];
__device__ __half g_qh[BMAX * KP];
__device__ int g_owner[NNODES];

__device__ int g_ht[HTSZ];
__device__ int g_uidtab[HTSZ];
__device__ int g_uelist[NSLOT];
__device__ int g_map[NSLOT];
__device__ int g_cnt;

// ---------------- helpers ----------------
__device__ __forceinline__ void cpa16(uint32_t dst, const void* src) {
  asm volatile("cp.async.cg.shared.global [%0], [%1], 16;" :: "r"(dst), "l"(src));
}
__device__ __forceinline__ void cpa_commit() { asm volatile("cp.async.commit_group;" ::: "memory"); }
template <int N>
__device__ __forceinline__ void cpa_wait() { asm volatile("cp.async.wait_group %0;" :: "n"(N) : "memory"); }

__device__ __forceinline__ void ldsm4(uint32_t* r, uint32_t addr) {
  asm volatile("ldmatrix.sync.aligned.m8n8.x4.shared.b16 {%0,%1,%2,%3}, [%4];"
               : "=r"(r[0]), "=r"(r[1]), "=r"(r[2]), "=r"(r[3]) : "r"(addr));
}
__device__ __forceinline__ void mma_f16(float* d, const uint32_t* a, const uint32_t* b) {
  asm volatile(
      "mma.sync.aligned.m16n8k16.row.col.f32.f16.f16.f32 "
      "{%0,%1,%2,%3},{%4,%5,%6,%7},{%8,%9},{%0,%1,%2,%3};"
      : "+f"(d[0]), "+f"(d[1]), "+f"(d[2]), "+f"(d[3])
      : "r"(a[0]), "r"(a[1]), "r"(a[2]), "r"(a[3]), "r"(b[0]), "r"(b[1]));
}

__device__ __forceinline__ void store4h(float4 v, __half* dst, size_t off) {
  __half2 a = __floats2half2_rn(v.x, v.y);
  __half2 b = __floats2half2_rn(v.z, v.w);
  ((__half2*)(dst + off))[0] = a;
  ((__half2*)(dst + off))[1] = b;
}

__device__ __forceinline__ uint32_t ehash(int e) {
  return (((uint32_t)e * 2654435761u) >> 13) & (HTSZ - 1);
}

// ---------------- small kernels ----------------
__global__ void init_owner_kernel() {
  int i = blockIdx.x * blockDim.x + threadIdx.x;
  if (i < NNODES) g_owner[i] = -1;
}
__global__ void build_owner_kernel(const int* __restrict__ nodes, int B) {
  int i = blockIdx.x * blockDim.x + threadIdx.x;
  if (i < B) atomicMax(&g_owner[nodes[i]], i);
}

// ---------------- edge dedup ----------------
__global__ void dedup1_kernel(const int* __restrict__ eidx, int n) {
  int i = blockIdx.x * blockDim.x + threadIdx.x;
  if (i >= n) return;
  int e = eidx[i];
  uint32_t h = ehash(e);
  while (true) {
    int prev = atomicCAS(&g_ht[h], -1, e);
    if (prev == -1 || prev == e) break;
    h = (h + 1) & (HTSZ - 1);
  }
}
__global__ void dedup2_kernel() {
  int i = blockIdx.x * blockDim.x + threadIdx.x;
  if (i >= HTSZ) return;
  int e = g_ht[i];
  if (e != -1) {
    int uid = atomicAdd(&g_cnt, 1);
    g_uidtab[i] = uid;
    g_uelist[uid] = e;
  }
}
__global__ void dedup3_kernel(const int* __restrict__ eidx, int n) {
  int i = blockIdx.x * blockDim.x + threadIdx.x;
  if (i >= n) return;
  int e = eidx[i];
  uint32_t h = ehash(e);
  while (g_ht[h] != e) h = (h + 1) & (HTSZ - 1);
  g_map[i] = g_uidtab[h];
}

// ---------------- weight packing ----------------
struct PArgs {
  const float* w[3];
  int ld[3];
  int coff[3];
  const float* bias[3];
};
__global__ void pack_w_kernel(PArgs a, int nseg, __half* wq, float* pbias) {
  int i = blockIdx.x * blockDim.x + threadIdx.x;
  int tot = nseg * NSEG * KP;
  if (i >= tot) return;
  int n = i / KP, c = i - n * KP;
  int seg = n / NSEG, nr = n - seg * NSEG;
  float v = 0.f;
  if (nr < E_ && c < E_) v = a.w[seg][(size_t)nr * a.ld[seg] + a.coff[seg] + c];
  wq[i] = __float2half_rn(v);
  if (c == 0) pbias[n] = (nr < E_ && a.bias[seg]) ? a.bias[seg][nr] : 0.f;
}

// composed Wc[n][d] = Wqkv[n]·out_w[:,d], bc[n] = Wqkv[n]·out_b
__global__ void compose_wc_kernel(const float* __restrict__ q_w,
                                  const float* __restrict__ k_w,
                                  const float* __restrict__ v_w,
                                  const float* __restrict__ out_w,
                                  const float* __restrict__ out_b) {
  int i = blockIdx.x * blockDim.x + threadIdx.x;
  if (i >= 576 * KP) return;
  int n = i / KP, d = i - n * KP;
  int seg = n / NSEG, nr = n - seg * NSEG;
  const float* wrow = nullptr;
  if (nr < E_)
    wrow = (seg == 0) ? q_w + (size_t)nr * E_
         : (seg == 1) ? k_w + (size_t)nr * (2 * E_)
                      : v_w + (size_t)nr * (2 * E_);
  float acc = 0.f;
  if (wrow && d < E_)
    for (int c = 0; c < E_; c++) acc += wrow[c] * out_w[(size_t)c * E_ + d];
  g_W[(size_t)(P6_OFF + n) * KP + d] = __float2half_rn(acc);
  if (d == 0) {
    float bb = 0.f;
    if (wrow)
      for (int c = 0; c < E_; c++) bb += wrow[c] * out_b[c];
    g_Wb[P6_OFF + n] = bb;
  }
}

// ---------------- vectorized converts ----------------
__global__ void convert_kernel(const float* __restrict__ X, int ldx,
                               const int* __restrict__ g1, int gmode,
                               int M, int Mpad, int rowoff) {
  int i = blockIdx.x * blockDim.x + threadIdx.x;
  if (i >= Mpad * C4) return;
  int r = i / C4, c4 = i - r * C4;
  float4 v = make_float4(0.f, 0.f, 0.f, 0.f);
  if (r < M && c4 < 43) {
    int src = (gmode >= 1) ? g1[r] : r;
    v = *(const float4*)(X + (size_t)src * ldx + c4 * 4);
  }
  store4h(v, g_A, (size_t)(rowoff + r) * KP + c4 * 4);
}

__global__ void convert_uedges_kernel(const float* __restrict__ ef) {
  int i = blockIdx.x * blockDim.x + threadIdx.x;
  if (i >= NSLOT * C4) return;
  int r = i / C4, c4 = i - r * C4;
  if (r >= g_cnt) return;
  float4 v = make_float4(0.f, 0.f, 0.f, 0.f);
  if (c4 < 43) v = *(const float4*)(ef + (size_t)g_uelist[r] * E_ + c4 * 4);
  store4h(v, g_A, (size_t)(R_EDGE + r) * KP + c4 * 4);
}

__global__ void timeconv_kernel(const float* __restrict__ ts,
                                const float* __restrict__ tw,
                                const float* __restrict__ tb, int B, int Mpad) {
  int i = blockIdx.x * blockDim.x + threadIdx.x;
  if (i >= Mpad * C4) return;
  int r = i / C4, c4 = i - r * C4;
  float4 v = make_float4(0.f, 0.f, 0.f, 0.f);
  if (r < B && c4 < 43) {
    float tval = ts[r];
    float4 w = *(const float4*)(tw + c4 * 4);
    float4 b = *(const float4*)(tb + c4 * 4);
    v.x = (float)cos((double)__fadd_rn(__fmul_rn(tval, w.x), b.x));
    v.y = (float)cos((double)__fadd_rn(__fmul_rn(tval, w.y), b.y));
    v.z = (float)cos((double)__fadd_rn(__fmul_rn(tval, w.z), b.z));
    v.w = (float)cos((double)__fadd_rn(__fmul_rn(tval, w.w), b.w));
  }
  store4h(v, g_A, (size_t)(R_TIME + r) * KP + c4 * 4);
}

// ---------------- pipelined fp16 HMMA GEMM ----------------
#define BM 128
#define BN 96
#define ST 24
#define STAGE_A_B (BM * ST * 2)
#define STAGE_B_B (BN * ST * 2)
#define SM_A  0
#define SM_B  (SM_A + 4 * STAGE_A_B)
#define SMEM_G (SM_B + 4 * STAGE_B_B)

__global__ __launch_bounds__(256, 2) void mma_gemm_kernel(
    const __half* __restrict__ A, const __half* __restrict__ W,
    const float* __restrict__ bias, float* __restrict__ outf,
    __half* __restrict__ outh,
    int M, int ldout, int segstride, int nwrite, const int* __restrict__ Mptr) {
  if (Mptr) {
    M = *Mptr;
    if ((int)(blockIdx.y * BM) >= M) return;
  }
  extern __shared__ __align__(128) char smraw[];
  const uint32_t sm = (uint32_t)__cvta_generic_to_shared(smraw);
  const int tid = threadIdx.x;
  const int warp = tid >> 5, lane = tid & 31;
  const int m0 = blockIdx.y * BM;
  const int n0 = blockIdx.x * BN;
  const int wm0 = (warp >> 1) * 32;
  const int wn0 = (warp & 1) * 48;

  float acc[2][6][4];
#pragma unroll
  for (int i = 0; i < 2; i++)
#pragma unroll
    for (int j = 0; j < 6; j++)
#pragma unroll
      for (int k = 0; k < 4; k++) acc[i][j][k] = 0.f;

  const int lr = tid >> 1, lch = tid & 1;
  const size_t srcA = (size_t)(m0 + lr) * KP + lch * 8;
  const size_t srcB = (size_t)(n0 + lr) * KP + lch * 8;
  const uint32_t dstAoff = (uint32_t)((lr * ST + lch * 8) * 2);
  const uint32_t dstBoff = dstAoff;

#define LOAD_STAGE(buf, ki)                                                 \
  do {                                                                      \
    cpa16(sm + SM_A + (buf) * STAGE_A_B + dstAoff, A + srcA + (ki) * 16);   \
    if (tid < 2 * BN)                                                       \
      cpa16(sm + SM_B + (buf) * STAGE_B_B + dstBoff, W + srcB + (ki) * 16); \
  } while (0)

  LOAD_STAGE(0, 0); cpa_commit();
  LOAD_STAGE(1, 1); cpa_commit();
  LOAD_STAGE(2, 2); cpa_commit();

  const int aRow = (lane & 7) + ((lane >> 3) & 1) * 8;
  const int aCol = ((lane >> 4) & 1) * 8;
  const int bRow = (lane & 7) + ((lane >> 4) & 1) * 8;
  const int bCol = ((lane >> 3) & 1) * 8;

  for (int ki = 0; ki < KSTEPS; ki++) {
    const int buf = ki & 3;
    cpa_wait<2>();
    __syncthreads();
    if (ki + 3 < KSTEPS) LOAD_STAGE((ki + 3) & 3, ki + 3);
    cpa_commit();

    const uint32_t aB = sm + SM_A + buf * STAGE_A_B;
    const uint32_t bB = sm + SM_B + buf * STAGE_B_B;

    uint32_t af[2][4], bf[6][2];
#pragma unroll
    for (int ti = 0; ti < 2; ti++) {
      uint32_t off = (uint32_t)(((wm0 + ti * 16 + aRow) * ST + aCol) * 2);
      ldsm4(af[ti], aB + off);
    }
#pragma unroll
    for (int p = 0; p < 3; p++) {
      uint32_t off = (uint32_t)(((wn0 + p * 16 + bRow) * ST + bCol) * 2);
      uint32_t t[4];
      ldsm4(t, bB + off);
      bf[2 * p][0] = t[0]; bf[2 * p][1] = t[1];
      bf[2 * p + 1][0] = t[2]; bf[2 * p + 1][1] = t[3];
    }
#pragma unroll
    for (int ti = 0; ti < 2; ti++)
#pragma unroll
      for (int nj = 0; nj < 6; nj++)
        mma_f16(acc[ti][nj], af[ti], bf[nj]);
  }
#undef LOAD_STAGE

  const int g = lane >> 2, tq = lane & 3;
#pragma unroll
  for (int ti = 0; ti < 2; ti++) {
    int m = m0 + wm0 + ti * 16 + g;
#pragma unroll
    for (int nj = 0; nj < 6; nj++) {
      int n = n0 + wn0 + nj * 8 + tq * 2;
      int seg = n / NSEG, nr = n - seg * NSEG;
      if (nr >= nwrite) continue;
      int col = seg * segstride + nr;
      float b0 = bias[n], b1 = bias[n + 1];
#pragma unroll
      for (int half = 0; half < 2; half++) {
        int mm = m + half * 8;
        if (mm >= M) continue;
        float v0 = acc[ti][nj][2 * half] + b0;
        float v1 = acc[ti][nj][2 * half + 1] + b1;
        if (outf) {
          *(float2*)(outf + (size_t)mm * ldout + col) = make_float2(v0, v1);
        } else {
          *(__half2*)(outh + (size_t)mm * ldout + col) = __floats2half2_rn(v0, v1);
        }
      }
    }
  }
}

// ---------------- attention (per sample), writes fp16 to R_O ----------------
template <int LAYER>
__global__ __launch_bounds__(256) void attn_kernel(const int* __restrict__ neighbors,
                                                   const int* __restrict__ nodes, int B) {
  __shared__ float q[E_];
  __shared__ __align__(16) float kk[KNB][E_];
  __shared__ float sc[HH][KNB];
  __shared__ float at[HH][KNB];
  __shared__ const __half* akp[KNB];
  __shared__ const __half* bkp[KNB];
  __shared__ int pad[KNB];

  const int b = blockIdx.x;
  const int tid = threadIdx.x;
  const __half* trow = g_tqkv + (size_t)b * 576;

  if (tid < KNB) {
    int nb = neighbors[b * KNB + tid];
    pad[tid] = (nb == 0) ? 1 : 0;
    const __half* ap = g_node_kv + (size_t)nb * 384;
    if (LAYER == 1) {
      int ow = g_owner[nb];
      if (ow >= 0) ap = g_l1out + (size_t)ow * 576 + 192;
    }
    akp[tid] = ap;
    bkp[tid] = g_edge_kv + (size_t)g_map[b * KNB + tid] * 384;
  }
  if (tid < E_) {
    float qh;
    if (LAYER == 0) {
      qh = __half2float(g_qh[(size_t)b * KP + tid]);
    } else {
      int ow = g_owner[nodes[b]];
      qh = __half2float(g_l1out[(size_t)ow * 576 + tid]);
    }
    q[tid] = qh + __half2float(trow[tid]);
  }
  __syncthreads();

  const __half* tk = trow + NSEG;
  for (int idx = tid; idx < KNB * 43; idx += 256) {
    int j = idx / 43, c4 = idx - j * 43;
    const __half2* a2 = (const __half2*)(akp[j] + c4 * 4);
    const __half2* e2 = (const __half2*)(bkp[j] + c4 * 4);
    const __half2* t2 = (const __half2*)(tk + c4 * 4);
    float2 a0 = __half22float2(a2[0]), a1 = __half22float2(a2[1]);
    float2 e0 = __half22float2(e2[0]), e1 = __half22float2(e2[1]);
    float2 t0 = __half22float2(t2[0]), t1 = __half22float2(t2[1]);
    float* dst = &kk[j][c4 * 4];
    dst[0] = a0.x + e0.x + t0.x;
    dst[1] = a0.y + e0.y + t0.y;
    dst[2] = a1.x + e1.x + t1.x;
    dst[3] = a1.y + e1.y + t1.y;
  }
  if (tid == 0) {
    int all = 1;
#pragma unroll
    for (int j = 0; j < KNB; j++) all &= pad[j];
    if (all) pad[0] = 0;
  }
  __syncthreads();

  if (tid < HH * KNB) {
    int h = tid / KNB, j = tid - h * KNB;
    const float* qp = q + h * HD_;
    const float* kp = &kk[j][h * HD_];
    float sum = 0.f;
#pragma unroll
    for (int d = 0; d < HD_; d++) sum += qp[d] * kp[d];
    sum *= 0.10783277320343841f;
    if (pad[j]) sum = -1e9f;
    sc[h][j] = sum;
  }
  __syncthreads();

  if (tid < HH) {
    float m = -INFINITY;
#pragma unroll
    for (int j = 0; j < KNB; j++) m = fmaxf(m, sc[tid][j]);
    float ex[KNB], ssum = 0.f;
#pragma unroll
    for (int j = 0; j < KNB; j++) { ex[j] = expf(sc[tid][j] - m); ssum += ex[j]; }
    float inv = 1.f / ssum;
#pragma unroll
    for (int j = 0; j < KNB; j++) at[tid][j] = ex[j] * inv;
  }
  __syncthreads();

  if (tid < E_) {
    int h = tid / HD_;
    float o = __half2float(trow[2 * NSEG + tid]);
#pragma unroll
    for (int j = 0; j < KNB; j++)
      o += at[h][j] * (__half2float(akp[j][NSEG + tid]) + __half2float(bkp[j][NSEG + tid]));
    g_A[(size_t)(R_O + b) * KP + tid] = __float2half_rn(o);
  }
}

// ---------------- launch ----------------
static inline int cdiv(int a, int b) { return (a + b - 1) / b; }

extern "C" void kernel_launch(void* const* d_in, const int* in_sizes, int n_in,
                              void* d_out, int out_size) {
  const int* nodes     = (const int*)d_in[0];
  const float* ts      = (const float*)d_in[1];
  const int* neighbors = (const int*)d_in[2];
  const int* eidx      = (const int*)d_in[3];
  const float* nf      = (const float*)d_in[4];
  const float* ef      = (const float*)d_in[5];
  const float* time_w  = (const float*)d_in[6];
  const float* time_b  = (const float*)d_in[7];
  const float* q_w     = (const float*)d_in[8];
  const float* k_w     = (const float*)d_in[9];
  const float* v_w     = (const float*)d_in[10];
  const float* bq      = (const float*)d_in[11];
  const float* bk      = (const float*)d_in[12];
  const float* bv      = (const float*)d_in[13];
  const float* out_w   = (const float*)d_in[14];
  const float* out_b   = (const float*)d_in[15];
  float* out = (float*)d_out;
  const int B = in_sizes[0];

  __half *pW, *pA, *pnodekv, *pedgekv, *pl1out, *ptqkv, *pqh;
  float *pWb;
  int *pht, *pcnt;
  cudaGetSymbolAddress((void**)&pW, g_W);
  cudaGetSymbolAddress((void**)&pWb, g_Wb);
  cudaGetSymbolAddress((void**)&pA, g_A);
  cudaGetSymbolAddress((void**)&ptqkv, g_tqkv);
  cudaGetSymbolAddress((void**)&pnodekv, g_node_kv);
  cudaGetSymbolAddress((void**)&pedgekv, g_edge_kv);
  cudaGetSymbolAddress((void**)&pl1out, g_l1out);
  cudaGetSymbolAddress((void**)&pqh, g_qh);
  cudaGetSymbolAddress((void**)&pht, g_ht);
  cudaGetSymbolAddress((void**)&pcnt, g_cnt);

  cudaFuncSetAttribute(mma_gemm_kernel, cudaFuncAttributeMaxDynamicSharedMemorySize, SMEM_G);

  static cudaStream_t s1 = nullptr;
  static cudaEvent_t evF = nullptr, evA, evB, evC, evQ;
  if (!s1) {
    cudaStreamCreateWithFlags(&s1, cudaStreamNonBlocking);
    cudaEventCreateWithFlags(&evF, cudaEventDisableTiming);
    cudaEventCreateWithFlags(&evA, cudaEventDisableTiming);
    cudaEventCreateWithFlags(&evB, cudaEventDisableTiming);
    cudaEventCreateWithFlags(&evC, cudaEventDisableTiming);
    cudaEventCreateWithFlags(&evQ, cudaEventDisableTiming);
  }
  cudaStream_t s0 = 0;

  PArgs p;

#define GEMM_F(strm, Mpad, Npad, poff, Aoff, outp, M, ldo, segs, nw, Mptr)    \
  mma_gemm_kernel<<<dim3((Npad) / BN, (Mpad) / BM), 256, SMEM_G, strm>>>(     \
      pA + (size_t)(Aoff) * KP, pW + (size_t)(poff) * KP,                     \
      pWb + (poff), outp, nullptr, M, ldo, segs, nw, Mptr)
#define GEMM_H(strm, Mpad, Npad, poff, Aoff, outp, M, ldo, segs, nw, Mptr)    \
  mma_gemm_kernel<<<dim3((Npad) / BN, (Mpad) / BM), 256, SMEM_G, strm>>>(     \
      pA + (size_t)(Aoff) * KP, pW + (size_t)(poff) * KP,                     \
      pWb + (poff), nullptr, outp, M, ldo, segs, nw, Mptr)

  // fork s1 from the capture stream
  cudaEventRecord(evF, s0);
  cudaStreamWaitEvent(s1, evF, 0);

  // ---- s1: prep, ordered by when s0 consumes it ----
  // group A: tqkv weights + time convert
  p.w[0] = q_w; p.ld[0] = E_;     p.coff[0] = 0; p.bias[0] = bq;
  p.w[1] = k_w; p.ld[1] = 2 * E_; p.coff[1] = 0; p.bias[1] = bk;
  p.w[2] = v_w; p.ld[2] = 2 * E_; p.coff[2] = 0; p.bias[2] = bv;
  pack_w_kernel<<<cdiv(3 * NSEG * KP, 256), 256, 0, s1>>>(p, 3, pW + (size_t)P1_OFF * KP, pWb + P1_OFF);
  timeconv_kernel<<<cdiv(BPAD * C4, 256), 256, 0, s1>>>(ts, time_w, time_b, B, BPAD);
  cudaEventRecord(evA, s1);
  // group B: node weights + node convert
  p.w[0] = k_w; p.ld[0] = 2 * E_; p.coff[0] = 0; p.bias[0] = nullptr;
  p.w[1] = v_w; p.ld[1] = 2 * E_; p.coff[1] = 0; p.bias[1] = nullptr;
  p.w[2] = nullptr; p.ld[2] = 0; p.coff[2] = 0; p.bias[2] = nullptr;
  pack_w_kernel<<<cdiv(2 * NSEG * KP, 256), 256, 0, s1>>>(p, 2, pW + (size_t)P2_OFF * KP, pWb + P2_OFF);
  convert_kernel<<<cdiv(NPADN * C4, 256), 256, 0, s1>>>(nf, E_, nullptr, 0, NNODES, NPADN, R_NODE);
  cudaEventRecord(evB, s1);
  // group C: edge dedup + edge weights + edge convert
  cudaMemsetAsync(pht, 0xFF, (size_t)HTSZ * sizeof(int), s1);
  cudaMemsetAsync(pcnt, 0, sizeof(int), s1);
  dedup1_kernel<<<cdiv(B * KNB, 256), 256, 0, s1>>>(eidx, B * KNB);
  dedup2_kernel<<<cdiv(HTSZ, 256), 256, 0, s1>>>();
  p.w[0] = k_w; p.ld[0] = 2 * E_; p.coff[0] = E_; p.bias[0] = nullptr;
  p.w[1] = v_w; p.ld[1] = 2 * E_; p.coff[1] = E_; p.bias[1] = nullptr;
  p.w[2] = nullptr;
  pack_w_kernel<<<cdiv(2 * NSEG * KP, 256), 256, 0, s1>>>(p, 2, pW + (size_t)P3_OFF * KP, pWb + P3_OFF);
  convert_uedges_kernel<<<cdiv(NSLOT * C4, 256), 256, 0, s1>>>(ef);
  cudaEventRecord(evC, s1);
  // group D (s1): dedup map, owner build, q/out packs, composed Wc, L0 q convert + GEMM
  dedup3_kernel<<<cdiv(B * KNB, 256), 256, 0, s1>>>(eidx, B * KNB);
  init_owner_kernel<<<cdiv(NNODES, 256), 256, 0, s1>>>();
  build_owner_kernel<<<cdiv(B, 256), 256, 0, s1>>>(nodes, B);
  p.w[0] = q_w; p.ld[0] = E_; p.coff[0] = 0; p.bias[0] = nullptr;
  p.w[1] = nullptr; p.w[2] = nullptr;
  pack_w_kernel<<<cdiv(NSEG * KP, 256), 256, 0, s1>>>(p, 1, pW + (size_t)P4_OFF * KP, pWb + P4_OFF);
  p.w[0] = out_w; p.bias[0] = out_b;
  pack_w_kernel<<<cdiv(NSEG * KP, 256), 256, 0, s1>>>(p, 1, pW + (size_t)P5_OFF * KP, pWb + P5_OFF);
  compose_wc_kernel<<<cdiv(576 * KP, 256), 256, 0, s1>>>(q_w, k_w, v_w, out_w, out_b);
  convert_kernel<<<cdiv(BPAD * C4, 256), 256, 0, s1>>>(nf, E_, nodes, 1, B, BPAD, R_Q0);
  GEMM_H(s1, BPAD, NSEG, P4_OFF, R_Q0, pqh, B, KP, 0, KP, nullptr);  // L0 q-proj on s1
  cudaEventRecord(evQ, s1);

  // ---- s0: GEMM chain + attention ----
  cudaStreamWaitEvent(s0, evA, 0);
  GEMM_H(s0, BPAD, 576, P1_OFF, R_TIME, ptqkv, B, 576, NSEG, NSEG, nullptr);
  cudaStreamWaitEvent(s0, evB, 0);
  GEMM_H(s0, NPADN, 384, P2_OFF, R_NODE, pnodekv, NNODES, 384, NSEG, NSEG, nullptr);
  cudaStreamWaitEvent(s0, evC, 0);
  GEMM_H(s0, NSLOT, 384, P3_OFF, R_EDGE, pedgekv, B * KNB, 384, NSEG, NSEG, pcnt);
  cudaStreamWaitEvent(s0, evQ, 0);

  // layer 0 attention
  attn_kernel<0><<<B, 256, 0, s0>>>(neighbors, nodes, B);

  // fused: l1out = attn0_out @ Wc^T + bc   (replaces out-proj GEMM + l1 GEMM)
  GEMM_H(s0, BPAD, 576, P6_OFF, R_O, pl1out, B, 576, NSEG, NSEG, nullptr);

  // layer 1 attention + final out-proj
  attn_kernel<1><<<B, 256, 0, s0>>>(neighbors, nodes, B);
  GEMM_F(s0, BPAD, NSEG, P5_OFF, R_O, out, B, E_, 0, E_, nullptr);
#undef GEMM_F
#undef GEMM_H
}